// round 12
// baseline (speedup 1.0000x reference)
#include <cuda_runtime.h>
#include <cuda_bf16.h>
#include <cstdint>
#include <math.h>

#define T_ 512
#define B_ 64
#define H_ 512
#define KK_ 16
#define M_ (T_*B_)       // 32768
#define NCHK 31          // 16-step chunk matrices per batch
#define LN2F 0.6931471805599453f

// ---------------- device scratch (allocation-free rule) ----------------
__device__ __nv_bfloat16 g_Xb[M_ * H_];    // 32 MB  X in bf16
__device__ __nv_bfloat16 g_W1T[H_ * H_];   // 0.5 MB W1^T in bf16
__device__ float g_em[M_ * KK_];           // 2 MB emissions (atomic-accumulated)
__device__ float g_P[B_ * NCHK * 16 * 16]; // chunk matrices, exp-form (global-max norm)
__device__ float g_R[B_ * NCHK];           // matrix log offsets (scalar per matrix)
__device__ float g_gold[B_];

// ---------------- helpers ----------------
__device__ __forceinline__ uint32_t smem_u32(const void* p) {
    uint32_t a;
    asm("{ .reg .u64 t; cvta.to.shared.u64 t, %1; cvt.u32.u64 %0, t; }"
        : "=r"(a) : "l"(p));
    return a;
}
__device__ __forceinline__ void cp_async16(uint32_t dst, const void* src) {
    asm volatile("cp.async.cg.shared.global [%0], [%1], 16;\n" :: "r"(dst), "l"(src));
}
#define CP_COMMIT() asm volatile("cp.async.commit_group;\n" ::: "memory")
#define CP_WAIT(n)  asm volatile("cp.async.wait_group %0;\n" :: "n"(n) : "memory")

__device__ __forceinline__ void mma16816(float* d, const uint32_t* a, const uint32_t* b) {
    asm volatile(
        "mma.sync.aligned.m16n8k16.row.col.f32.bf16.bf16.f32 "
        "{%0,%1,%2,%3}, {%4,%5,%6,%7}, {%8,%9}, {%0,%1,%2,%3};\n"
        : "+f"(d[0]), "+f"(d[1]), "+f"(d[2]), "+f"(d[3])
        : "r"(a[0]), "r"(a[1]), "r"(a[2]), "r"(a[3]), "r"(b[0]), "r"(b[1]));
}
__device__ __forceinline__ void ldsm_x4(uint32_t* r, uint32_t addr) {
    asm volatile("ldmatrix.sync.aligned.m8n8.x4.shared.b16 {%0,%1,%2,%3}, [%4];\n"
                 : "=r"(r[0]), "=r"(r[1]), "=r"(r[2]), "=r"(r[3]) : "r"(addr));
}
__device__ __forceinline__ uint32_t packbf(float a, float b) {
    __nv_bfloat162 h = __floats2bfloat162_rn(a, b);
    return *(uint32_t*)&h;
}
__device__ __forceinline__ float dot16(
    const float* t, float4 b0, float4 b1, float4 b2, float4 b3)
{
    float s0 = t[0] * b0.x, s1 = t[1] * b0.y, s2 = t[2] * b0.z, s3 = t[3] * b0.w;
    s0 = fmaf(t[4],  b1.x, s0); s1 = fmaf(t[5],  b1.y, s1);
    s2 = fmaf(t[6],  b1.z, s2); s3 = fmaf(t[7],  b1.w, s3);
    s0 = fmaf(t[8],  b2.x, s0); s1 = fmaf(t[9],  b2.y, s1);
    s2 = fmaf(t[10], b2.z, s2); s3 = fmaf(t[11], b2.w, s3);
    s0 = fmaf(t[12], b3.x, s0); s1 = fmaf(t[13], b3.y, s1);
    s2 = fmaf(t[14], b3.z, s2); s3 = fmaf(t[15], b3.w, s3);
    return (s0 + s1) + (s2 + s3);
}

// ---------------------------------------------------------------------------
// Fused prep kernel (one launch)
// ---------------------------------------------------------------------------
#define PREP_CONVX   16384
#define PREP_INITEM  (PREP_CONVX + 512)
#define PREP_TOTAL   (PREP_INITEM + 256)

__global__ __launch_bounds__(256) void prep_kernel(
    const float* __restrict__ X, const float* __restrict__ W1,
    const float* __restrict__ b2, float* __restrict__ out)
{
    const int bid = blockIdx.x;
    const int tid = threadIdx.x;

    if (bid < PREP_CONVX) {
        size_t i = ((size_t)bid * 256 + tid) * 4;
        float4 v = *(const float4*)(X + i);
        uint2 u;
        u.x = packbf(v.x, v.y);
        u.y = packbf(v.z, v.w);
        *(uint2*)(g_Xb + i) = u;
    } else if (bid < PREP_INITEM) {
        if (bid == PREP_CONVX && tid == 0) out[0] = 0.f;
        size_t i = ((size_t)(bid - PREP_CONVX) * 256 + tid) * 4;
        const int ph = (int)(i & 15);
        float4 v;
        v.x = b2[ph]; v.y = b2[ph + 1]; v.z = b2[ph + 2]; v.w = b2[ph + 3];
        *(float4*)(g_em + i) = v;
    } else {
        __shared__ float t[32][33];
        const int tb = bid - PREP_INITEM;
        const int bx = (tb & 15) * 32, by = (tb >> 4) * 32;
        const int x = tid & 31, y = tid >> 5;   // 32 x 8
#pragma unroll
        for (int i = 0; i < 4; i++)
            t[y + i * 8][x] = W1[(size_t)(by + y + i * 8) * H_ + bx + x];
        __syncthreads();
#pragma unroll
        for (int i = 0; i < 4; i++)
            g_W1T[(size_t)(bx + y + i * 8) * H_ + by + x] =
                __float2bfloat16(t[x][y + i * 8]);
    }
}

// ---------------------------------------------------------------------------
// K1: fused  h = relu(X@W1+b1);  em += h @ W2   (unchanged; passing since R7)
// ---------------------------------------------------------------------------
#define BM 128
#define BN 128
#define BK 32
#define NKC (H_/BK)           // 16
#define ROWW 20
#define TILE_WORDS (BM*ROWW)
#define STAGE_WORDS (2*TILE_WORDS)
#define SMEM_BYTES (4*STAGE_WORDS*4)   // 81920

__global__ __launch_bounds__(256, 2) void gemm1_fused(
    const float* __restrict__ b1, const float* __restrict__ W2)
{
    extern __shared__ uint32_t sw[];
    const uint32_t sb = smem_u32(sw);
    const int tid  = threadIdx.x;
    const int wid  = tid >> 5, lane = tid & 31;
    const int g    = lane >> 2, t = lane & 3;
    const int wm   = wid >> 2;
    const int wn   = wid & 3;
    const int ks   = wid & 1;
    const int row0 = blockIdx.y * BM;
    const int col0 = blockIdx.x * BN;

    auto issue_stage = [&](int c, int s) {
        const int k0 = c * BK;
        const uint32_t base = (uint32_t)(s * STAGE_WORDS);
#pragma unroll
        for (int q = 0; q < 2; q++) {
            const int u   = tid + q * 256;
            const int row = u >> 2, seg = u & 3;
            cp_async16(sb + (base + row * ROWW + seg * 4) * 4,
                       g_Xb + (size_t)(row0 + row) * H_ + k0 + seg * 8);
        }
#pragma unroll
        for (int q = 0; q < 2; q++) {
            const int u   = tid + q * 256;
            const int row = u >> 2, seg = u & 3;
            cp_async16(sb + (base + TILE_WORDS + row * ROWW + seg * 4) * 4,
                       g_W1T + (size_t)(col0 + row) * H_ + k0 + seg * 8);
        }
    };

    issue_stage(0, 0); CP_COMMIT();
    issue_stage(1, 1); CP_COMMIT();
    issue_stage(2, 2); CP_COMMIT();

    const int r8    = lane & 7;
    const int aWOff = ((wm * 64 + r8 + (((lane >> 3) & 1) << 3)) * ROWW)
                    + ((lane >> 4) << 2);
    const int bWOff = TILE_WORDS
                    + ((wn * 32 + r8 + (((lane >> 4) & 1) << 3)) * ROWW)
                    + (((lane >> 3) & 1) << 2);

    float acc[4][4][4];
#pragma unroll
    for (int i = 0; i < 4; i++)
#pragma unroll
        for (int j = 0; j < 4; j++)
#pragma unroll
            for (int r = 0; r < 4; r++) acc[i][j][r] = 0.f;

    for (int c = 0; c < NKC; c++) {
        if (c <= NKC - 3)      CP_WAIT(2);
        else if (c == NKC - 2) CP_WAIT(1);
        else                   CP_WAIT(0);
        __syncthreads();
        if (c + 3 < NKC) { issue_stage(c + 3, (c + 3) & 3); CP_COMMIT(); }

        const uint32_t stg = sb + (uint32_t)(c & 3) * (STAGE_WORDS * 4);

#pragma unroll
        for (int kk2 = 0; kk2 < 2; kk2++) {
            const int kk = kk2 ^ ks;
            const int kw = kk * 8;
            uint32_t af[4][4], bf[4][2];
#pragma unroll
            for (int i = 0; i < 4; i++)
                ldsm_x4(af[i], stg + (uint32_t)(aWOff + i * 16 * ROWW + kw) * 4);
#pragma unroll
            for (int p = 0; p < 2; p++) {
                uint32_t br[4];
                ldsm_x4(br, stg + (uint32_t)(bWOff + p * 16 * ROWW + kw) * 4);
                bf[2*p][0]   = br[0]; bf[2*p][1]   = br[1];
                bf[2*p+1][0] = br[2]; bf[2*p+1][1] = br[3];
            }
#pragma unroll
            for (int i = 0; i < 4; i++)
#pragma unroll
                for (int j = 0; j < 4; j++)
                    mma16816(acc[i][j], af[i], bf[j]);
        }
    }

#pragma unroll
    for (int j = 0; j < 4; j++) {
        const int col = col0 + wn * 32 + j * 8 + 2 * t;
        const float bb0 = __ldg(b1 + col), bb1 = __ldg(b1 + col + 1);
#pragma unroll
        for (int i = 0; i < 4; i++) {
            acc[i][j][0] = fmaxf(acc[i][j][0] + bb0, 0.f);
            acc[i][j][1] = fmaxf(acc[i][j][1] + bb1, 0.f);
            acc[i][j][2] = fmaxf(acc[i][j][2] + bb0, 0.f);
            acc[i][j][3] = fmaxf(acc[i][j][3] + bb1, 0.f);
        }
    }

    uint32_t bw[2][2][2];
    {
        const int kb0 = col0 + wn * 32;
#pragma unroll
        for (int jp = 0; jp < 2; jp++)
#pragma unroll
            for (int nt = 0; nt < 2; nt++) {
                const int kb = kb0 + jp * 16;
                const int n  = nt * 8 + g;
                float w0 = __ldg(W2 + (size_t)(kb + 2*t)     * KK_ + n);
                float w1 = __ldg(W2 + (size_t)(kb + 2*t + 1) * KK_ + n);
                float w2v= __ldg(W2 + (size_t)(kb + 2*t + 8) * KK_ + n);
                float w3 = __ldg(W2 + (size_t)(kb + 2*t + 9) * KK_ + n);
                bw[jp][nt][0] = packbf(w0, w1);
                bw[jp][nt][1] = packbf(w2v, w3);
            }
    }

    __syncthreads();
    float* em_s = (float*)sw;

#pragma unroll
    for (int i = 0; i < 4; i++) {
        float e0[4] = {0.f, 0.f, 0.f, 0.f};
        float e1[4] = {0.f, 0.f, 0.f, 0.f};
#pragma unroll
        for (int jp = 0; jp < 2; jp++) {
            uint32_t af_[4];
            af_[0] = packbf(acc[i][2*jp][0],   acc[i][2*jp][1]);
            af_[1] = packbf(acc[i][2*jp][2],   acc[i][2*jp][3]);
            af_[2] = packbf(acc[i][2*jp+1][0], acc[i][2*jp+1][1]);
            af_[3] = packbf(acc[i][2*jp+1][2], acc[i][2*jp+1][3]);
            mma16816(e0, af_, bw[jp][0]);
            mma16816(e1, af_, bw[jp][1]);
        }
        const int r = wm * 64 + i * 16 + g;
        float* sl  = em_s + (size_t)(wn * 128 + r) * 18;
        float* sl8 = em_s + (size_t)(wn * 128 + r + 8) * 18;
        *(float2*)(sl  + 2*t)     = make_float2(e0[0], e0[1]);
        *(float2*)(sl  + 8 + 2*t) = make_float2(e1[0], e1[1]);
        *(float2*)(sl8 + 2*t)     = make_float2(e0[2], e0[3]);
        *(float2*)(sl8 + 8 + 2*t) = make_float2(e1[2], e1[3]);
    }
    __syncthreads();

#pragma unroll
    for (int q = 0; q < 8; q++) {
        const int o = tid + q * 256;
        const int r = o >> 4, n = o & 15;
        float s = em_s[(size_t)(0 * 128 + r) * 18 + n]
                + em_s[(size_t)(1 * 128 + r) * 18 + n]
                + em_s[(size_t)(2 * 128 + r) * 18 + n]
                + em_s[(size_t)(3 * 128 + r) * 18 + n];
        atomicAdd(g_em + (size_t)(row0 + r) * KK_ + n, s);
    }
}

// ---------------------------------------------------------------------------
// Scan phase 1: chunk matrices (linear chains, exponent-trick norm) +
// gold path (blockIdx.x == NCHK).
// ---------------------------------------------------------------------------
__global__ __launch_bounds__(256) void scan_p1(
    const float* __restrict__ trans, const int* __restrict__ lens,
    const int* __restrict__ tags)
{
    const int c = blockIdx.x, b = blockIdx.y;
    const int tid = threadIdx.x;

    if (c == NCHK) {   // ---- gold path for batch b ----
        __shared__ float wsum[8];
        const int len = lens[b];
        float v = 0.f;
#pragma unroll
        for (int h = 0; h < 2; h++) {
            const int t = tid + h * 256;
            if (t < len) {
                const int tag = tags[t * B_ + b];
                float x = g_em[(size_t)(t * B_ + b) * KK_ + tag];
                if (t > 0) x += trans[tag * KK_ + tags[(t - 1) * B_ + b]];
                v += x;
            }
        }
#pragma unroll
        for (int off = 16; off; off >>= 1)
            v += __shfl_xor_sync(0xffffffffu, v, off);
        if ((tid & 31) == 0) wsum[tid >> 5] = v;
        __syncthreads();
        if (tid == 0) {
            float s = 0.f;
#pragma unroll
            for (int i = 0; i < 8; i++) s += wsum[i];
            g_gold[b] = s;
        }
        return;
    }

    // ---- chunk chain ----
    const int wid  = tid >> 5, lane = tid & 31;
    const int jj   = lane & 15;
    const int col  = wid * 2 + (lane >> 4);

    __shared__ float es[16][16];
    __shared__ float cm[16][17];
    __shared__ float rms[16];
    __shared__ __align__(16) float xW[2][16][16];

    {
        const int tt = tid >> 4, k = tid & 15;
        es[tt][k] = g_em[(size_t)((16*c + 1 + tt) * B_ + b) * KK_ + k];
    }
    float4 T0, T1, T2, T3;
    {
        float te[16];
#pragma unroll
        for (int i = 0; i < 16; i++) te[i] = __expf(trans[jj * KK_ + i]);
        T0 = make_float4(te[0], te[1], te[2], te[3]);
        T1 = make_float4(te[4], te[5], te[6], te[7]);
        T2 = make_float4(te[8], te[9], te[10], te[11]);
        T3 = make_float4(te[12], te[13], te[14], te[15]);
    }
    const float tr_own = trans[jj * KK_ + col];
    const float tr_0   = trans[col];            // trans[0][col]
    __syncthreads();

    float Lbase = tr_0 + es[0][0];
    int   Lexp  = 0;
    float w_own = __expf(tr_own + es[0][jj] - Lbase);
    xW[0][col][jj] = w_own;
    __syncwarp();
    float t[16];
    {
        const float4 u0 = *(const float4*)(xW[0][col] + 0);
        const float4 u1 = *(const float4*)(xW[0][col] + 4);
        const float4 u2 = *(const float4*)(xW[0][col] + 8);
        const float4 u3 = *(const float4*)(xW[0][col] + 12);
        t[0]=u0.x; t[1]=u0.y; t[2]=u0.z; t[3]=u0.w;
        t[4]=u1.x; t[5]=u1.y; t[6]=u1.z; t[7]=u1.w;
        t[8]=u2.x; t[9]=u2.y; t[10]=u2.z; t[11]=u2.w;
        t[12]=u3.x; t[13]=u3.y; t[14]=u3.z; t[15]=u3.w;
    }
    float inv_last = 1.f;
    int pb = 1;

#pragma unroll 1
    for (int tt = 1; tt < 16; tt++) {
        const float em0 = es[tt][0];
        const float esc = __expf(es[tt][jj] - em0);
        const float w = dot16(t, T0, T1, T2, T3) * esc;
        xW[pb][col][jj] = w;
        __syncwarp();
        const float w0 = xW[pb][col][0];
        const int   e  = ((__float_as_int(w0) >> 23) & 255) - 127;
        const float inv = __int_as_float((uint32_t)(127 - e) << 23);
        Lbase += em0; Lexp += e;
        const float4 u0 = *(const float4*)(xW[pb][col] + 0);
        const float4 u1 = *(const float4*)(xW[pb][col] + 4);
        const float4 u2 = *(const float4*)(xW[pb][col] + 8);
        const float4 u3 = *(const float4*)(xW[pb][col] + 12);
        t[0]=u0.x*inv; t[1]=u0.y*inv; t[2]=u0.z*inv; t[3]=u0.w*inv;
        t[4]=u1.x*inv; t[5]=u1.y*inv; t[6]=u1.z*inv; t[7]=u1.w*inv;
        t[8]=u2.x*inv; t[9]=u2.y*inv; t[10]=u2.z*inv; t[11]=u2.w*inv;
        t[12]=u3.x*inv; t[13]=u3.y*inv; t[14]=u3.z*inv; t[15]=u3.w*inv;
        w_own = w; inv_last = inv;
        pb ^= 1;
    }
    cm[col][jj] = Lbase + (float)Lexp * LN2F + __logf(w_own * inv_last);
    __syncthreads();

    if (tid < 16) {
        float rm = cm[0][tid];
#pragma unroll
        for (int i = 1; i < 16; i++) rm = fmaxf(rm, cm[i][tid]);
        rms[tid] = rm;
    }
    __syncthreads();
    if (tid < 16) {
        float gmax = rms[0];
#pragma unroll
        for (int i = 1; i < 16; i++) gmax = fmaxf(gmax, rms[i]);
        float o[16];
#pragma unroll
        for (int i = 0; i < 16; i++)
            o[i] = __expf(cm[i][tid] - gmax);
        float* dst = g_P + (size_t)((b * NCHK + c) * 16 + tid) * 16;
#pragma unroll
        for (int q = 0; q < 4; q++)
            *(float4*)(dst + q * 4) =
                make_float4(o[4*q], o[4*q+1], o[4*q+2], o[4*q+3]);
        if (tid == 0) g_R[b * NCHK + c] = gmax;
    }
}

// ---------------------------------------------------------------------------
// Scan phase 2: 4 lanes per batch, register-double-buffered P, no MUFU in
// the chunk loop (power-of-2 renorm), fixed trip counts + predicated commit.
// grid = 4 blocks x 64 threads (16 batches per block).
// ---------------------------------------------------------------------------
__global__ __launch_bounds__(64) void scan_p2(
    const float* __restrict__ trans, const int* __restrict__ lens,
    float* __restrict__ out)
{
    const int tid = threadIdx.x;
    const int b   = blockIdx.x * 16 + (tid >> 2);
    const int q   = tid & 3;                 // rows 4q..4q+3
    const int len   = lens[b];
    const int last  = len - 1;
    const int nfull = last >> 4;             // 15..31
    const int nrem  = last & 15;

    __shared__ __align__(16) float sEx[64][4];
    __shared__ float sRed[16];

    float t[16];
    float Lbase;
    int   Lexp = 0;
    {
        const float* em = g_em + (size_t)b * KK_;
        Lbase = em[0];
#pragma unroll
        for (int i = 0; i < 16; i++)
            t[i] = __expf(em[i] - Lbase);
    }

    float4 PA[16], PB[16];
    auto loadP = [&](float4* P, int c) {
        const float* src = g_P + ((size_t)(b * NCHK + c) * 16 + 4 * q) * 16;
#pragma unroll
        for (int r = 0; r < 4; r++)
#pragma unroll
            for (int u = 0; u < 4; u++)
                P[r * 4 + u] = *(const float4*)(src + r * 16 + u * 4);
    };

    auto stepM = [&](const float4* P, float Radd, float4 esc, bool commit) {
        float w[4];
#pragma unroll
        for (int r = 0; r < 4; r++)
            w[r] = dot16(t, P[r*4], P[r*4+1], P[r*4+2], P[r*4+3]);
        w[0] *= esc.x; w[1] *= esc.y; w[2] *= esc.z; w[3] *= esc.w;
        *(float4*)sEx[tid] = make_float4(w[0], w[1], w[2], w[3]);
        __syncwarp();
        float tn[16];
#pragma unroll
        for (int s = 0; s < 4; s++) {
            const float4 v = *(const float4*)sEx[(tid & ~3) + s];
            tn[s*4+0] = v.x; tn[s*4+1] = v.y; tn[s*4+2] = v.z; tn[s*4+3] = v.w;
        }
        const int e = ((__float_as_int(tn[0]) >> 23) & 255) - 127;
        const float inv = __int_as_float((uint32_t)(127 - e) << 23);
        if (commit) {
            Lbase += Radd; Lexp += e;
#pragma unroll
            for (int i = 0; i < 16; i++) t[i] = tn[i] * inv;
        }
    };

    const float4 one4 = make_float4(1.f, 1.f, 1.f, 1.f);

    // ---- chunk combines: fixed 31 trips, double-buffered, predicated ----
    loadP(PA, 0);
#pragma unroll 1
    for (int c2 = 0; c2 < 16; c2++) {
        const int c = 2 * c2;
        if (c + 1 < NCHK) loadP(PB, c + 1);
        stepM(PA, g_R[b * NCHK + c], one4, c < nfull);
        if (c + 1 < NCHK) {
            if (c + 2 < NCHK) loadP(PA, c + 2);
            stepM(PB, g_R[b * NCHK + c + 1], one4, (c + 1) < nfull);
        }
    }

    // ---- load exp(trans) rows into PA (raw; |trans| small) ----
#pragma unroll
    for (int r = 0; r < 4; r++)
#pragma unroll
        for (int u = 0; u < 4; u++) {
            const float4 tv = *(const float4*)(trans + (4*q + r) * KK_ + 4*u);
            PA[r*4+u] = make_float4(__expf(tv.x), __expf(tv.y),
                                    __expf(tv.z), __expf(tv.w));
        }

    // ---- elementary remainder: fixed 15 trips, predicated ----
#pragma unroll 1
    for (int s = 0; s < 15; s++) {
        const int tt = 16 * nfull + 1 + s;     // <= 511 always
        const float* em = g_em + (size_t)(tt * B_ + b) * KK_;
        const float em0 = em[0];
        const float4 ev = *(const float4*)(em + 4 * q);
        float4 esc;
        esc.x = __expf(ev.x - em0);
        esc.y = __expf(ev.y - em0);
        esc.z = __expf(ev.z - em0);
        esc.w = __expf(ev.w - em0);
        stepM(PA, em0, esc, s < nrem);
    }

    // ---- final logsumexp + output ----
    float ssum = 0.f;
#pragma unroll
    for (int i = 0; i < 16; i++) ssum += t[i];
    const float fwd = Lbase + (float)Lexp * LN2F + __logf(ssum);

    if (q == 0) sRed[tid >> 2] = fwd - g_gold[b];
    __syncthreads();
    if (tid == 0) {
        float a = 0.f;
#pragma unroll
        for (int i = 0; i < 16; i++) a += sRed[i];
        atomicAdd(out, a);
    }
}

// ---------------------------------------------------------------------------
extern "C" void kernel_launch(void* const* d_in, const int* in_sizes, int n_in,
                              void* d_out, int out_size)
{
    (void)in_sizes; (void)n_in; (void)out_size;
    const float* hidden = (const float*)d_in[0];
    const float* W1     = (const float*)d_in[1];
    const float* b1     = (const float*)d_in[2];
    const float* W2     = (const float*)d_in[3];
    const float* b2     = (const float*)d_in[4];
    const float* trans  = (const float*)d_in[5];
    const int*   lens   = (const int*)d_in[6];
    const int*   tags   = (const int*)d_in[7];

    cudaFuncSetAttribute(gemm1_fused, cudaFuncAttributeMaxDynamicSharedMemorySize,
                         SMEM_BYTES);

    prep_kernel<<<PREP_TOTAL, 256>>>(hidden, W1, b2, (float*)d_out);
    gemm1_fused<<<dim3(H_ / BN, M_ / BM), 256, SMEM_BYTES>>>(b1, W2);
    scan_p1<<<dim3(NCHK + 1, B_), 256>>>(trans, lens, tags);
    scan_p2<<<4, 64>>>(trans, lens, (float*)d_out);
}

// round 13
// speedup vs baseline: 1.1517x; 1.1517x over previous
#include <cuda_runtime.h>
#include <cuda_bf16.h>
#include <cstdint>
#include <math.h>

#define T_ 512
#define B_ 64
#define H_ 512
#define KK_ 16
#define M_ (T_*B_)       // 32768
#define NCHK 31          // 16-step chunk matrices per batch
#define LN2F 0.6931471805599453f

// ---------------- device scratch (allocation-free rule) ----------------
__device__ __nv_bfloat16 g_Xb[M_ * H_];    // 32 MB  X in bf16
__device__ __nv_bfloat16 g_W1T[H_ * H_];   // 0.5 MB W1^T in bf16
__device__ float g_em[M_ * KK_];           // 2 MB emissions (atomic-accumulated)
__device__ float g_P[B_ * NCHK * 16 * 16]; // chunk matrices, exp-form (global-max norm)
__device__ float g_R[B_ * NCHK];           // matrix log offsets
__device__ float g_Pp[B_ * 16 * 16];       // partial (tail) matrices
__device__ float g_Rp[B_];                 // partial log offsets
__device__ float g_gold[B_];

// ---------------- helpers ----------------
__device__ __forceinline__ uint32_t smem_u32(const void* p) {
    uint32_t a;
    asm("{ .reg .u64 t; cvta.to.shared.u64 t, %1; cvt.u32.u64 %0, t; }"
        : "=r"(a) : "l"(p));
    return a;
}
__device__ __forceinline__ void cp_async16(uint32_t dst, const void* src) {
    asm volatile("cp.async.cg.shared.global [%0], [%1], 16;\n" :: "r"(dst), "l"(src));
}
#define CP_COMMIT() asm volatile("cp.async.commit_group;\n" ::: "memory")
#define CP_WAIT(n)  asm volatile("cp.async.wait_group %0;\n" :: "n"(n) : "memory")

__device__ __forceinline__ void mma16816(float* d, const uint32_t* a, const uint32_t* b) {
    asm volatile(
        "mma.sync.aligned.m16n8k16.row.col.f32.bf16.bf16.f32 "
        "{%0,%1,%2,%3}, {%4,%5,%6,%7}, {%8,%9}, {%0,%1,%2,%3};\n"
        : "+f"(d[0]), "+f"(d[1]), "+f"(d[2]), "+f"(d[3])
        : "r"(a[0]), "r"(a[1]), "r"(a[2]), "r"(a[3]), "r"(b[0]), "r"(b[1]));
}
__device__ __forceinline__ void ldsm_x4(uint32_t* r, uint32_t addr) {
    asm volatile("ldmatrix.sync.aligned.m8n8.x4.shared.b16 {%0,%1,%2,%3}, [%4];\n"
                 : "=r"(r[0]), "=r"(r[1]), "=r"(r[2]), "=r"(r[3]) : "r"(addr));
}
__device__ __forceinline__ uint32_t packbf(float a, float b) {
    __nv_bfloat162 h = __floats2bfloat162_rn(a, b);
    return *(uint32_t*)&h;
}
__device__ __forceinline__ float dot16(
    const float* t, float4 b0, float4 b1, float4 b2, float4 b3)
{
    float s0 = t[0] * b0.x, s1 = t[1] * b0.y, s2 = t[2] * b0.z, s3 = t[3] * b0.w;
    s0 = fmaf(t[4],  b1.x, s0); s1 = fmaf(t[5],  b1.y, s1);
    s2 = fmaf(t[6],  b1.z, s2); s3 = fmaf(t[7],  b1.w, s3);
    s0 = fmaf(t[8],  b2.x, s0); s1 = fmaf(t[9],  b2.y, s1);
    s2 = fmaf(t[10], b2.z, s2); s3 = fmaf(t[11], b2.w, s3);
    s0 = fmaf(t[12], b3.x, s0); s1 = fmaf(t[13], b3.y, s1);
    s2 = fmaf(t[14], b3.z, s2); s3 = fmaf(t[15], b3.w, s3);
    return (s0 + s1) + (s2 + s3);
}

// ---------------------------------------------------------------------------
// Fused prep kernel (one launch)
// ---------------------------------------------------------------------------
#define PREP_CONVX   16384
#define PREP_INITEM  (PREP_CONVX + 512)
#define PREP_TOTAL   (PREP_INITEM + 256)

__global__ __launch_bounds__(256) void prep_kernel(
    const float* __restrict__ X, const float* __restrict__ W1,
    const float* __restrict__ b2, float* __restrict__ out)
{
    const int bid = blockIdx.x;
    const int tid = threadIdx.x;

    if (bid < PREP_CONVX) {
        size_t i = ((size_t)bid * 256 + tid) * 4;
        float4 v = *(const float4*)(X + i);
        uint2 u;
        u.x = packbf(v.x, v.y);
        u.y = packbf(v.z, v.w);
        *(uint2*)(g_Xb + i) = u;
    } else if (bid < PREP_INITEM) {
        if (bid == PREP_CONVX && tid == 0) out[0] = 0.f;
        size_t i = ((size_t)(bid - PREP_CONVX) * 256 + tid) * 4;
        const int ph = (int)(i & 15);
        float4 v;
        v.x = b2[ph]; v.y = b2[ph + 1]; v.z = b2[ph + 2]; v.w = b2[ph + 3];
        *(float4*)(g_em + i) = v;
    } else {
        __shared__ float t[32][33];
        const int tb = bid - PREP_INITEM;
        const int bx = (tb & 15) * 32, by = (tb >> 4) * 32;
        const int x = tid & 31, y = tid >> 5;   // 32 x 8
#pragma unroll
        for (int i = 0; i < 4; i++)
            t[y + i * 8][x] = W1[(size_t)(by + y + i * 8) * H_ + bx + x];
        __syncthreads();
#pragma unroll
        for (int i = 0; i < 4; i++)
            g_W1T[(size_t)(bx + y + i * 8) * H_ + by + x] =
                __float2bfloat16(t[x][y + i * 8]);
    }
}

// ---------------------------------------------------------------------------
// K1: fused  h = relu(X@W1+b1);  em += h @ W2   (unchanged; passing since R7)
// ---------------------------------------------------------------------------
#define BM 128
#define BN 128
#define BK 32
#define NKC (H_/BK)           // 16
#define ROWW 20
#define TILE_WORDS (BM*ROWW)
#define STAGE_WORDS (2*TILE_WORDS)
#define SMEM_BYTES (4*STAGE_WORDS*4)   // 81920

__global__ __launch_bounds__(256, 2) void gemm1_fused(
    const float* __restrict__ b1, const float* __restrict__ W2)
{
    extern __shared__ uint32_t sw[];
    const uint32_t sb = smem_u32(sw);
    const int tid  = threadIdx.x;
    const int wid  = tid >> 5, lane = tid & 31;
    const int g    = lane >> 2, t = lane & 3;
    const int wm   = wid >> 2;
    const int wn   = wid & 3;
    const int ks   = wid & 1;
    const int row0 = blockIdx.y * BM;
    const int col0 = blockIdx.x * BN;

    auto issue_stage = [&](int c, int s) {
        const int k0 = c * BK;
        const uint32_t base = (uint32_t)(s * STAGE_WORDS);
#pragma unroll
        for (int q = 0; q < 2; q++) {
            const int u   = tid + q * 256;
            const int row = u >> 2, seg = u & 3;
            cp_async16(sb + (base + row * ROWW + seg * 4) * 4,
                       g_Xb + (size_t)(row0 + row) * H_ + k0 + seg * 8);
        }
#pragma unroll
        for (int q = 0; q < 2; q++) {
            const int u   = tid + q * 256;
            const int row = u >> 2, seg = u & 3;
            cp_async16(sb + (base + TILE_WORDS + row * ROWW + seg * 4) * 4,
                       g_W1T + (size_t)(col0 + row) * H_ + k0 + seg * 8);
        }
    };

    issue_stage(0, 0); CP_COMMIT();
    issue_stage(1, 1); CP_COMMIT();
    issue_stage(2, 2); CP_COMMIT();

    const int r8    = lane & 7;
    const int aWOff = ((wm * 64 + r8 + (((lane >> 3) & 1) << 3)) * ROWW)
                    + ((lane >> 4) << 2);
    const int bWOff = TILE_WORDS
                    + ((wn * 32 + r8 + (((lane >> 4) & 1) << 3)) * ROWW)
                    + (((lane >> 3) & 1) << 2);

    float acc[4][4][4];
#pragma unroll
    for (int i = 0; i < 4; i++)
#pragma unroll
        for (int j = 0; j < 4; j++)
#pragma unroll
            for (int r = 0; r < 4; r++) acc[i][j][r] = 0.f;

    for (int c = 0; c < NKC; c++) {
        if (c <= NKC - 3)      CP_WAIT(2);
        else if (c == NKC - 2) CP_WAIT(1);
        else                   CP_WAIT(0);
        __syncthreads();
        if (c + 3 < NKC) { issue_stage(c + 3, (c + 3) & 3); CP_COMMIT(); }

        const uint32_t stg = sb + (uint32_t)(c & 3) * (STAGE_WORDS * 4);

#pragma unroll
        for (int kk2 = 0; kk2 < 2; kk2++) {
            const int kk = kk2 ^ ks;
            const int kw = kk * 8;
            uint32_t af[4][4], bf[4][2];
#pragma unroll
            for (int i = 0; i < 4; i++)
                ldsm_x4(af[i], stg + (uint32_t)(aWOff + i * 16 * ROWW + kw) * 4);
#pragma unroll
            for (int p = 0; p < 2; p++) {
                uint32_t br[4];
                ldsm_x4(br, stg + (uint32_t)(bWOff + p * 16 * ROWW + kw) * 4);
                bf[2*p][0]   = br[0]; bf[2*p][1]   = br[1];
                bf[2*p+1][0] = br[2]; bf[2*p+1][1] = br[3];
            }
#pragma unroll
            for (int i = 0; i < 4; i++)
#pragma unroll
                for (int j = 0; j < 4; j++)
                    mma16816(acc[i][j], af[i], bf[j]);
        }
    }

#pragma unroll
    for (int j = 0; j < 4; j++) {
        const int col = col0 + wn * 32 + j * 8 + 2 * t;
        const float bb0 = __ldg(b1 + col), bb1 = __ldg(b1 + col + 1);
#pragma unroll
        for (int i = 0; i < 4; i++) {
            acc[i][j][0] = fmaxf(acc[i][j][0] + bb0, 0.f);
            acc[i][j][1] = fmaxf(acc[i][j][1] + bb1, 0.f);
            acc[i][j][2] = fmaxf(acc[i][j][2] + bb0, 0.f);
            acc[i][j][3] = fmaxf(acc[i][j][3] + bb1, 0.f);
        }
    }

    uint32_t bw[2][2][2];
    {
        const int kb0 = col0 + wn * 32;
#pragma unroll
        for (int jp = 0; jp < 2; jp++)
#pragma unroll
            for (int nt = 0; nt < 2; nt++) {
                const int kb = kb0 + jp * 16;
                const int n  = nt * 8 + g;
                float w0 = __ldg(W2 + (size_t)(kb + 2*t)     * KK_ + n);
                float w1 = __ldg(W2 + (size_t)(kb + 2*t + 1) * KK_ + n);
                float w2v= __ldg(W2 + (size_t)(kb + 2*t + 8) * KK_ + n);
                float w3 = __ldg(W2 + (size_t)(kb + 2*t + 9) * KK_ + n);
                bw[jp][nt][0] = packbf(w0, w1);
                bw[jp][nt][1] = packbf(w2v, w3);
            }
    }

    __syncthreads();
    float* em_s = (float*)sw;

#pragma unroll
    for (int i = 0; i < 4; i++) {
        float e0[4] = {0.f, 0.f, 0.f, 0.f};
        float e1[4] = {0.f, 0.f, 0.f, 0.f};
#pragma unroll
        for (int jp = 0; jp < 2; jp++) {
            uint32_t af_[4];
            af_[0] = packbf(acc[i][2*jp][0],   acc[i][2*jp][1]);
            af_[1] = packbf(acc[i][2*jp][2],   acc[i][2*jp][3]);
            af_[2] = packbf(acc[i][2*jp+1][0], acc[i][2*jp+1][1]);
            af_[3] = packbf(acc[i][2*jp+1][2], acc[i][2*jp+1][3]);
            mma16816(e0, af_, bw[jp][0]);
            mma16816(e1, af_, bw[jp][1]);
        }
        const int r = wm * 64 + i * 16 + g;
        float* sl  = em_s + (size_t)(wn * 128 + r) * 18;
        float* sl8 = em_s + (size_t)(wn * 128 + r + 8) * 18;
        *(float2*)(sl  + 2*t)     = make_float2(e0[0], e0[1]);
        *(float2*)(sl  + 8 + 2*t) = make_float2(e1[0], e1[1]);
        *(float2*)(sl8 + 2*t)     = make_float2(e0[2], e0[3]);
        *(float2*)(sl8 + 8 + 2*t) = make_float2(e1[2], e1[3]);
    }
    __syncthreads();

#pragma unroll
    for (int q = 0; q < 8; q++) {
        const int o = tid + q * 256;
        const int r = o >> 4, n = o & 15;
        float s = em_s[(size_t)(0 * 128 + r) * 18 + n]
                + em_s[(size_t)(1 * 128 + r) * 18 + n]
                + em_s[(size_t)(2 * 128 + r) * 18 + n]
                + em_s[(size_t)(3 * 128 + r) * 18 + n];
        atomicAdd(g_em + (size_t)(row0 + r) * KK_ + n, s);
    }
}

// ---------------------------------------------------------------------------
// Scan phase 1: chunk matrices + tail-partial matrices + gold path.
// blockIdx.x: 0..30 = chunks, 31 = tail pseudo-chunk, 32 = gold.
// ---------------------------------------------------------------------------
__global__ __launch_bounds__(256) void scan_p1(
    const float* __restrict__ trans, const int* __restrict__ lens,
    const int* __restrict__ tags)
{
    const int c = blockIdx.x, b = blockIdx.y;
    const int tid = threadIdx.x;

    if (c == NCHK + 1) {   // ---- gold path ----
        __shared__ float wsum[8];
        const int len = lens[b];
        float v = 0.f;
#pragma unroll
        for (int h = 0; h < 2; h++) {
            const int t = tid + h * 256;
            if (t < len) {
                const int tag = tags[t * B_ + b];
                float x = g_em[(size_t)(t * B_ + b) * KK_ + tag];
                if (t > 0) x += trans[tag * KK_ + tags[(t - 1) * B_ + b]];
                v += x;
            }
        }
#pragma unroll
        for (int off = 16; off; off >>= 1)
            v += __shfl_xor_sync(0xffffffffu, v, off);
        if ((tid & 31) == 0) wsum[tid >> 5] = v;
        __syncthreads();
        if (tid == 0) {
            float s = 0.f;
#pragma unroll
            for (int i = 0; i < 8; i++) s += wsum[i];
            g_gold[b] = s;
        }
        return;
    }

    // ---- chunk chain (c <= NCHK; c == NCHK is tail-partial-only) ----
    const int last  = lens[b] - 1;
    const int nfb   = last >> 4;
    const int nrb   = last & 15;
    const bool need_partial = (c == nfb) && (nrb > 0);
    const int stash_tt = need_partial ? (nrb - 1) : -2;

    if (c == NCHK && !need_partial) return;   // pseudo-chunk unused

    const int wid  = tid >> 5, lane = tid & 31;
    const int jj   = lane & 15;
    const int col  = wid * 2 + (lane >> 4);

    __shared__ float es[16][16];
    __shared__ float cm[16][17];
    __shared__ float cmp[16][17];
    __shared__ float rms[16];
    __shared__ float rmsp[16];
    __shared__ __align__(16) float xW[2][16][16];

    {
        const int tt = tid >> 4, k = tid & 15;
        int tload = 16 * c + 1 + tt;
        if (tload > T_ - 1) tload = T_ - 1;    // clamp (only pseudo-chunk tail)
        es[tt][k] = g_em[(size_t)(tload * B_ + b) * KK_ + k];
    }
    float4 T0, T1, T2, T3;
    {
        float te[16];
#pragma unroll
        for (int i = 0; i < 16; i++) te[i] = __expf(trans[jj * KK_ + i]);
        T0 = make_float4(te[0], te[1], te[2], te[3]);
        T1 = make_float4(te[4], te[5], te[6], te[7]);
        T2 = make_float4(te[8], te[9], te[10], te[11]);
        T3 = make_float4(te[12], te[13], te[14], te[15]);
    }
    const float tr_own = trans[jj * KK_ + col];
    const float tr_0   = trans[col];
    __syncthreads();

    float Lbase = tr_0 + es[0][0];
    int   Lexp  = 0;
    float w_own = __expf(tr_own + es[0][jj] - Lbase);
    if (stash_tt == -1 + 1 && need_partial && nrb == 1)   // never true; placeholder
        ;
    if (need_partial && nrb == 1)
        cmp[col][jj] = tr_own + es[0][jj];
    xW[0][col][jj] = w_own;
    __syncwarp();
    float t[16];
    {
        const float4 u0 = *(const float4*)(xW[0][col] + 0);
        const float4 u1 = *(const float4*)(xW[0][col] + 4);
        const float4 u2 = *(const float4*)(xW[0][col] + 8);
        const float4 u3 = *(const float4*)(xW[0][col] + 12);
        t[0]=u0.x; t[1]=u0.y; t[2]=u0.z; t[3]=u0.w;
        t[4]=u1.x; t[5]=u1.y; t[6]=u1.z; t[7]=u1.w;
        t[8]=u2.x; t[9]=u2.y; t[10]=u2.z; t[11]=u2.w;
        t[12]=u3.x; t[13]=u3.y; t[14]=u3.z; t[15]=u3.w;
    }
    float inv_last = 1.f;
    int pb = 1;

#pragma unroll 1
    for (int tt = 1; tt < 16; tt++) {
        const float em0 = es[tt][0];
        const float esc = __expf(es[tt][jj] - em0);
        const float w = dot16(t, T0, T1, T2, T3) * esc;
        xW[pb][col][jj] = w;
        __syncwarp();
        const float w0 = xW[pb][col][0];
        const int   e  = ((__float_as_int(w0) >> 23) & 255) - 127;
        const float inv = __int_as_float((uint32_t)(127 - e) << 23);
        Lbase += em0; Lexp += e;
        const float4 u0 = *(const float4*)(xW[pb][col] + 0);
        const float4 u1 = *(const float4*)(xW[pb][col] + 4);
        const float4 u2 = *(const float4*)(xW[pb][col] + 8);
        const float4 u3 = *(const float4*)(xW[pb][col] + 12);
        t[0]=u0.x*inv; t[1]=u0.y*inv; t[2]=u0.z*inv; t[3]=u0.w*inv;
        t[4]=u1.x*inv; t[5]=u1.y*inv; t[6]=u1.z*inv; t[7]=u1.w*inv;
        t[8]=u2.x*inv; t[9]=u2.y*inv; t[10]=u2.z*inv; t[11]=u2.w*inv;
        t[12]=u3.x*inv; t[13]=u3.y*inv; t[14]=u3.z*inv; t[15]=u3.w*inv;
        w_own = w; inv_last = inv;
        if (tt == stash_tt)
            cmp[col][jj] = Lbase + (float)Lexp * LN2F + __logf(w_own * inv_last);
        pb ^= 1;
    }
    cm[col][jj] = Lbase + (float)Lexp * LN2F + __logf(w_own * inv_last);
    __syncthreads();

    if (c < NCHK) {
        if (tid < 16) {
            float rm = cm[0][tid];
#pragma unroll
            for (int i = 1; i < 16; i++) rm = fmaxf(rm, cm[i][tid]);
            rms[tid] = rm;
        }
    }
    if (need_partial && tid < 16) {
        float rm = cmp[0][tid];
#pragma unroll
        for (int i = 1; i < 16; i++) rm = fmaxf(rm, cmp[i][tid]);
        rmsp[tid] = rm;
    }
    __syncthreads();
    if (c < NCHK && tid < 16) {
        float gmax = rms[0];
#pragma unroll
        for (int i = 1; i < 16; i++) gmax = fmaxf(gmax, rms[i]);
        float o[16];
#pragma unroll
        for (int i = 0; i < 16; i++)
            o[i] = __expf(cm[i][tid] - gmax);
        float* dst = g_P + (size_t)((b * NCHK + c) * 16 + tid) * 16;
#pragma unroll
        for (int q = 0; q < 4; q++)
            *(float4*)(dst + q * 4) =
                make_float4(o[4*q], o[4*q+1], o[4*q+2], o[4*q+3]);
        if (tid == 0) g_R[b * NCHK + c] = gmax;
    }
    if (need_partial && tid < 16) {
        float gmax = rmsp[0];
#pragma unroll
        for (int i = 1; i < 16; i++) gmax = fmaxf(gmax, rmsp[i]);
        float o[16];
#pragma unroll
        for (int i = 0; i < 16; i++)
            o[i] = __expf(cmp[i][tid] - gmax);
        float* dst = g_Pp + (size_t)(b * 16 + tid) * 16;
#pragma unroll
        for (int q = 0; q < 4; q++)
            *(float4*)(dst + q * 4) =
                make_float4(o[4*q], o[4*q+1], o[4*q+2], o[4*q+3]);
        if (tid == 0) g_Rp[b] = gmax;
    }
}

// ---------------------------------------------------------------------------
// Scan phase 2: per-batch prefix MATRIX chain, 256 threads per batch.
// Each serial step = 16x16x16 matmul (1 elem/thread), 1 barrier/step,
// register-prefetched B, power-of-2 renorm (no MUFU in loop).
// ---------------------------------------------------------------------------
__global__ __launch_bounds__(256) void scan_p2(
    const int* __restrict__ lens, float* __restrict__ out)
{
    const int b   = blockIdx.x;
    const int tid = threadIdx.x;
    const int j = tid >> 4, i = tid & 15;
    const int last  = lens[b] - 1;
    const int nfull = last >> 4;             // 15..31
    const int nrem  = last & 15;
    const int nsteps = (nfull - 1) + (nrem ? 1 : 0);

    __shared__ __align__(16) float A[2][16][17];
    __shared__ float red[8];

    // pre-sum R offsets (off critical path)
    float Lsum = g_R[b * NCHK];
    for (int c = 1; c < nfull; c++) Lsum += g_R[b * NCHK + c];
    if (nrem) Lsum += g_Rp[b];
    int Lexp = 0;

    A[0][j][i] = g_P[((size_t)(b * NCHK) * 16 + j) * 16 + i];
    __syncthreads();

    float Bc[16];
    {
        const float* p = (1 <= nfull - 1)
            ? g_P + ((size_t)(b * NCHK + 1) * 16 + j) * 16
            : g_Pp + (size_t)(b * 16 + j) * 16;
#pragma unroll
        for (int k = 0; k < 16; k++) Bc[k] = p[k];
    }

    int pb = 0;
#pragma unroll 1
    for (int s = 1; s <= nsteps; s++) {
        float Bn[16];
        if (s + 1 <= nsteps) {
            const float* p = (s + 1 <= nfull - 1)
                ? g_P + ((size_t)(b * NCHK + s + 1) * 16 + j) * 16
                : g_Pp + (size_t)(b * 16 + j) * 16;
#pragma unroll
            for (int k = 0; k < 16; k++) Bn[k] = p[k];
        } else {
#pragma unroll
            for (int k = 0; k < 16; k++) Bn[k] = 0.f;
        }
        const float A00 = A[pb][0][0];
        const int   e   = ((__float_as_int(A00) >> 23) & 255) - 127;
        const float inv = __int_as_float((uint32_t)(127 - e) << 23);
        float sd = 0.f;
#pragma unroll
        for (int k = 0; k < 16; k++)
            sd = fmaf(Bc[k], A[pb][k][i], sd);
        A[pb ^ 1][j][i] = sd * inv;
        Lexp += e;
        __syncthreads();
        pb ^= 1;
#pragma unroll
        for (int k = 0; k < 16; k++) Bc[k] = Bn[k];
    }

    // epilogue: fwd = Lsum + Lexp*ln2 + m0 + log sum_{j,i} A_ji * w_i
    const float* em = g_em + (size_t)b * KK_;
    const float m0  = em[0];
    const float w0i = __expf(em[i] - m0);
    const float A00 = A[pb][0][0];
    const int   e   = ((__float_as_int(A00) >> 23) & 255) - 127;
    const float inv = __int_as_float((uint32_t)(127 - e) << 23);
    float v = A[pb][j][i] * inv * w0i;
    Lexp += e;
#pragma unroll
    for (int off = 16; off; off >>= 1)
        v += __shfl_xor_sync(0xffffffffu, v, off);
    if ((tid & 31) == 0) red[tid >> 5] = v;
    __syncthreads();
    if (tid == 0) {
        float tot = 0.f;
#pragma unroll
        for (int w = 0; w < 8; w++) tot += red[w];
        const float fwd = Lsum + (float)Lexp * LN2F + m0 + __logf(tot);
        atomicAdd(out, fwd - g_gold[b]);
    }
}

// ---------------------------------------------------------------------------
extern "C" void kernel_launch(void* const* d_in, const int* in_sizes, int n_in,
                              void* d_out, int out_size)
{
    (void)in_sizes; (void)n_in; (void)out_size;
    const float* hidden = (const float*)d_in[0];
    const float* W1     = (const float*)d_in[1];
    const float* b1     = (const float*)d_in[2];
    const float* W2     = (const float*)d_in[3];
    const float* b2     = (const float*)d_in[4];
    const float* trans  = (const float*)d_in[5];
    const int*   lens   = (const int*)d_in[6];
    const int*   tags   = (const int*)d_in[7];

    cudaFuncSetAttribute(gemm1_fused, cudaFuncAttributeMaxDynamicSharedMemorySize,
                         SMEM_BYTES);

    prep_kernel<<<PREP_TOTAL, 256>>>(hidden, W1, b2, (float*)d_out);
    gemm1_fused<<<dim3(H_ / BN, M_ / BM), 256, SMEM_BYTES>>>(b1, W2);
    scan_p1<<<dim3(NCHK + 2, B_), 256>>>(trans, lens, tags);
    scan_p2<<<B_, 256>>>(lens, (float*)d_out);
}